// round 5
// baseline (speedup 1.0000x reference)
#include <cuda_runtime.h>
#include <math.h>

#define HW 65536
#define IMG 256
#define CIN 256
#define CMID 64
#define NB 4

// Scratch (device globals; allocation is forbidden)
__device__ float g_y[NB * CMID * HW];      // conv1x1-in output (64 MiB)
__device__ float g_edge[NB * CMID * HW];   // unnormalized edge  (64 MiB)
__device__ unsigned g_maxbits;             // global max (float bits, values >= 0)
__device__ float g_csum[NB * CMID];        // per-(b,c) sums of edge
__device__ float g_seff[NB * CMID];        // sigmoid(se)*inv_max per (b,c)

// 1D gaussian (sigma=2, size=5), normalized: exp(-r^2/8)/sum
#define G0 0.15246915f
#define G1 0.22184120f
#define G2 0.25137913f

__global__ void k_init() {
    int t = threadIdx.x;
    if (t == 0) g_maxbits = 0u;
    if (t < NB * CMID) g_csum[t] = 0.0f;
}

// ---------------------------------------------------------------------------
// Stage A: y[b,o,p] = b_in[o] + sum_c x[b,c,p] * w_in[o,c]
// Block: 256 threads, 256 pixels, each thread all 64 outputs for one pixel.
// Weights staged in smem in [c][o] layout in two 128-c chunks (32 KB).
// ---------------------------------------------------------------------------
__global__ __launch_bounds__(256, 2)
void k_conv_in(const float* __restrict__ x, const float* __restrict__ w_in,
               const float* __restrict__ b_in) {
    __shared__ float sw[128 * 64];
    const int tid = threadIdx.x;
    const int b = blockIdx.y;
    const int p = blockIdx.x * 256 + tid;
    const float* xp = x + (size_t)b * CIN * HW + p;

    float acc[64];
#pragma unroll
    for (int o = 0; o < 64; o++) acc[o] = __ldg(b_in + o);

    for (int half = 0; half < 2; half++) {
        __syncthreads();
        // sw[c*64+o] = w_in[o*256 + half*128 + c]; consecutive tid -> consecutive o
        for (int idx = tid; idx < 128 * 64; idx += 256) {
            int c = idx >> 6, o = idx & 63;
            sw[idx] = __ldg(w_in + o * CIN + half * 128 + c);
        }
        __syncthreads();
        const float* xh = xp + (size_t)(half * 128) * HW;
#pragma unroll 4
        for (int c = 0; c < 128; c++) {
            float xv = __ldg(xh + (size_t)c * HW);
            const float4* wr = (const float4*)(sw + (c << 6));
#pragma unroll
            for (int i = 0; i < 16; i++) {
                float4 w4 = wr[i];
                acc[4 * i + 0] += xv * w4.x;
                acc[4 * i + 1] += xv * w4.y;
                acc[4 * i + 2] += xv * w4.z;
                acc[4 * i + 3] += xv * w4.w;
            }
        }
    }
    float* yp = g_y + (size_t)b * CMID * HW + p;
#pragma unroll
    for (int o = 0; o < 64; o++) yp[(size_t)o * HW] = acc[o];
}

// ---------------------------------------------------------------------------
// Stage B: per (b,c) plane, 32x32 tiles with radius-3 halo:
//   sm = gauss5x5(y) (separable), edge = max(|scharr0|,|scharr90|) + 0.1|lap|
// sm samples outside the image are ZERO (reference zero-pads sm for the 3x3s).
// Also reduces global max and per-plane sum.
// ---------------------------------------------------------------------------
__global__ __launch_bounds__(256)
void k_edge() {
    __shared__ float sy[38 * 40];   // y tile + halo(3), padded width
    __shared__ float sh[38 * 34];   // horizontally blurred
    __shared__ float s2[34 * 36];   // fully blurred sm (tile + halo 1)
    __shared__ float red[256];

    const int tid = threadIdx.x;
    const int z = blockIdx.z;                  // b*64 + ch
    const int ty = blockIdx.y, tx = blockIdx.x;
    const float* yp = g_y + (size_t)z * HW;
    const int gy0 = ty * 32 - 3, gx0 = tx * 32 - 3;

    // load 38x38 input with zero OOB
    for (int idx = tid; idx < 38 * 38; idx += 256) {
        int r = idx / 38, c = idx % 38;
        int gy = gy0 + r, gx = gx0 + c;
        float v = 0.0f;
        if (gy >= 0 && gy < IMG && gx >= 0 && gx < IMG) v = yp[gy * IMG + gx];
        sy[r * 40 + c] = v;
    }
    __syncthreads();

    // horizontal gaussian: 38 rows x 34 cols
    for (int idx = tid; idx < 38 * 34; idx += 256) {
        int r = idx / 34, c = idx % 34;
        const float* row = sy + r * 40 + c;
        sh[idx] = G0 * (row[0] + row[4]) + G1 * (row[1] + row[3]) + G2 * row[2];
    }
    __syncthreads();

    // vertical gaussian: 34x34, masked to zero outside image
    for (int idx = tid; idx < 34 * 34; idx += 256) {
        int r = idx / 34, c = idx % 34;
        int gy = ty * 32 + r - 1, gx = tx * 32 + c - 1;
        float v = 0.0f;
        if (gy >= 0 && gy < IMG && gx >= 0 && gx < IMG) {
            const float* col = sh + r * 34 + c;
            v = G0 * (col[0] + col[4 * 34]) + G1 * (col[34] + col[3 * 34])
                + G2 * col[2 * 34];
        }
        s2[r * 36 + c] = v;
    }
    __syncthreads();

    float tmax = 0.0f, tsum = 0.0f;
    float* ep = g_edge + (size_t)z * HW;
#pragma unroll
    for (int q = 0; q < 4; q++) {
        int idx = q * 256 + tid;
        int i = idx >> 5, j = idx & 31;
        const float* s = s2 + i * 36 + j;
        float nw = s[0],  nn = s[1],  ne = s[2];
        float ww = s[36], cc = s[37], ee = s[38];
        float sw_ = s[72], ss = s[73], se = s[74];
        float gx = 3.0f * (nw - ne) + 10.0f * (ww - ee) + 3.0f * (sw_ - se);
        float gy = 3.0f * (nw - sw_) + 10.0f * (nn - ss) + 3.0f * (ne - se);
        float lap = 4.0f * cc - nn - ss - ww - ee;
        float e = fmaxf(fabsf(gx), fabsf(gy)) + 0.1f * fabsf(lap);
        ep[(ty * 32 + i) * IMG + tx * 32 + j] = e;
        tmax = fmaxf(tmax, e);
        tsum += e;
    }

    // block reduce max then sum
    red[tid] = tmax;
    __syncthreads();
    for (int s = 128; s; s >>= 1) {
        if (tid < s) red[tid] = fmaxf(red[tid], red[tid + s]);
        __syncthreads();
    }
    if (tid == 0) atomicMax(&g_maxbits, __float_as_uint(red[0]));
    __syncthreads();
    red[tid] = tsum;
    __syncthreads();
    for (int s = 128; s; s >>= 1) {
        if (tid < s) red[tid] += red[tid + s];
        __syncthreads();
    }
    if (tid == 0) atomicAdd(&g_csum[z], red[0]);
}

// ---------------------------------------------------------------------------
// Stage C: SE head. pooled = mean(edge_norm) = csum/65536 * inv_max.
// g_seff[b,c] = sigmoid(fc2(relu(fc1(pooled)))) * inv_max
// ---------------------------------------------------------------------------
__global__ void k_se(const float* __restrict__ w_fc1, const float* __restrict__ b_fc1,
                     const float* __restrict__ w_fc2, const float* __restrict__ b_fc2) {
    __shared__ float pooled[NB * CMID];
    __shared__ float hbuf[NB * 4];
    const int tid = threadIdx.x;
    const float maxv = __uint_as_float(g_maxbits);
    const float inv = 1.0f / (maxv + 1e-8f);

    pooled[tid] = g_csum[tid] * inv * (1.0f / 65536.0f);
    __syncthreads();
    if (tid < NB * 4) {
        int b = tid >> 2, j = tid & 3;
        float a = b_fc1[j];
        for (int c = 0; c < 64; c++) a += w_fc1[j * 64 + c] * pooled[b * 64 + c];
        hbuf[tid] = a > 0.0f ? a : 0.0f;
    }
    __syncthreads();
    {
        int b = tid >> 6, c = tid & 63;
        float a = b_fc2[c];
        for (int j = 0; j < 4; j++) a += w_fc2[c * 4 + j] * hbuf[b * 4 + j];
        float sc = 1.0f / (1.0f + expf(-a));
        g_seff[tid] = sc * inv;
    }
}

// ---------------------------------------------------------------------------
// Stage D: out[b,o,p] = b_out[o] + sum_c (edge[b,c,p]*seff[b,c]) * w_out[o,c]
// ---------------------------------------------------------------------------
__global__ __launch_bounds__(256, 2)
void k_conv_out(const float* __restrict__ w_out, const float* __restrict__ b_out,
                float* __restrict__ out) {
    __shared__ float sw[64 * 64];
    __shared__ float ssc[64];
    const int tid = threadIdx.x;
    const int b = blockIdx.y;

    for (int idx = tid; idx < 4096; idx += 256) {
        int c = idx >> 6, o = idx & 63;
        sw[idx] = __ldg(w_out + o * 64 + c);
    }
    if (tid < 64) ssc[tid] = g_seff[b * 64 + tid];
    __syncthreads();

    const int p = blockIdx.x * 256 + tid;
    const float* ep = g_edge + (size_t)b * CMID * HW + p;
    float acc[64];
#pragma unroll
    for (int o = 0; o < 64; o++) acc[o] = __ldg(b_out + o);

#pragma unroll 2
    for (int c = 0; c < 64; c++) {
        float xv = ep[(size_t)c * HW] * ssc[c];
        const float4* wr = (const float4*)(sw + (c << 6));
#pragma unroll
        for (int i = 0; i < 16; i++) {
            float4 w4 = wr[i];
            acc[4 * i + 0] += xv * w4.x;
            acc[4 * i + 1] += xv * w4.y;
            acc[4 * i + 2] += xv * w4.z;
            acc[4 * i + 3] += xv * w4.w;
        }
    }
    float* op = out + (size_t)b * CMID * HW + p;
#pragma unroll
    for (int o = 0; o < 64; o++) op[(size_t)o * HW] = acc[o];
}

// ---------------------------------------------------------------------------
extern "C" void kernel_launch(void* const* d_in, const int* in_sizes, int n_in,
                              void* d_out, int out_size) {
    const float* x     = (const float*)d_in[0];
    const float* w_in  = (const float*)d_in[1];
    const float* b_in  = (const float*)d_in[2];
    const float* w_fc1 = (const float*)d_in[3];
    const float* b_fc1 = (const float*)d_in[4];
    const float* w_fc2 = (const float*)d_in[5];
    const float* b_fc2 = (const float*)d_in[6];
    const float* w_out = (const float*)d_in[7];
    const float* b_out = (const float*)d_in[8];
    float* out = (float*)d_out;

    k_init<<<1, 256>>>();
    dim3 ga(256, NB);
    k_conv_in<<<ga, 256>>>(x, w_in, b_in);
    dim3 gb(8, 8, NB * CMID);
    k_edge<<<gb, 256>>>();
    k_se<<<1, 256>>>(w_fc1, b_fc1, w_fc2, b_fc2);
    dim3 gd(256, NB);
    k_conv_out<<<gd, 256>>>(w_out, b_out, out);
}

// round 6
// speedup vs baseline: 2.0867x; 2.0867x over previous
#include <cuda_runtime.h>
#include <cuda_bf16.h>
#include <cstdint>
#include <math.h>

#define HW 65536
#define IMG 256
#define CIN 256
#define CMID 64
#define NB 4

// Scratch (device globals; allocation is forbidden)
__device__ float g_y[NB * CMID * HW];      // conv1x1-in output (64 MiB)
__device__ float g_edge[NB * CMID * HW];   // unnormalized edge  (64 MiB)
__device__ unsigned g_maxbits;             // global max (float bits, values >= 0)
__device__ float g_csum[NB * CMID];        // per-(b,c) sums of edge
__device__ float g_seff[NB * CMID];        // sigmoid(se)*inv_max per (b,c)

// Pre-split weights (bf16 hi/lo)
__device__ __align__(16) __nv_bfloat16 g_win_hi[64 * 256];
__device__ __align__(16) __nv_bfloat16 g_win_lo[64 * 256];
__device__ __align__(16) __nv_bfloat16 g_wout_hi[64 * 64];
__device__ __align__(16) __nv_bfloat16 g_wout_lo[64 * 64];

// 1D gaussian (sigma=2, size=5), normalized: exp(-r^2/8)/sum
#define G0 0.15246915f
#define G1 0.22184120f
#define G2 0.25137913f

__global__ void k_init() {
    int t = threadIdx.x;
    if (t == 0) g_maxbits = 0u;
    if (t < NB * CMID) g_csum[t] = 0.0f;
}

// Split fp32 weights into bf16 hi/lo pairs.
__global__ void k_prep(const float* __restrict__ w_in, const float* __restrict__ w_out) {
    int i = blockIdx.x * 256 + threadIdx.x;
    if (i < 64 * 256) {
        float w = w_in[i];
        __nv_bfloat16 h = __float2bfloat16_rn(w);
        g_win_hi[i] = h;
        g_win_lo[i] = __float2bfloat16_rn(w - __bfloat162float(h));
    }
    if (i < 64 * 64) {
        float w = w_out[i];
        __nv_bfloat16 h = __float2bfloat16_rn(w);
        g_wout_hi[i] = h;
        g_wout_lo[i] = __float2bfloat16_rn(w - __bfloat162float(h));
    }
}

// ---------------------------------------------------------------------------
// Tensor-core 1x1 conv:  Y[b,o,p] = bias[o] + sum_c W[o,c] * X[b,c,p]
// M=64 (o), N_TILE=64 pixels, K=CK. 3-GEMM bf16 split for fp32-grade accuracy.
// 8 warps, each warp: m32 x n16. K processed in chunks of 64 with LDG prefetch.
// SCALE=true: X = g_edge scaled by g_seff[b][c], Y = external out (conv_out).
// SCALE=false: X = x input, Y = g_y (conv_in).
// ---------------------------------------------------------------------------
__device__ __forceinline__ void mma_bf16(float* d, const uint32_t* a, const uint32_t* b) {
    asm volatile(
        "mma.sync.aligned.m16n8k16.row.col.f32.bf16.bf16.f32 "
        "{%0,%1,%2,%3}, {%4,%5,%6,%7}, {%8,%9}, {%0,%1,%2,%3};\n"
        : "+f"(d[0]), "+f"(d[1]), "+f"(d[2]), "+f"(d[3])
        : "r"(a[0]), "r"(a[1]), "r"(a[2]), "r"(a[3]), "r"(b[0]), "r"(b[1]));
}
__device__ __forceinline__ void ldsm_x4(uint32_t* r, uint32_t addr) {
    asm volatile("ldmatrix.sync.aligned.m8n8.x4.shared.b16 {%0,%1,%2,%3}, [%4];"
                 : "=r"(r[0]), "=r"(r[1]), "=r"(r[2]), "=r"(r[3]) : "r"(addr));
}
__device__ __forceinline__ void ldsm_x2t(uint32_t* r, uint32_t addr) {
    asm volatile("ldmatrix.sync.aligned.m8n8.x2.trans.shared.b16 {%0,%1}, [%2];"
                 : "=r"(r[0]), "=r"(r[1]) : "r"(addr));
}

template <int CK, bool SCALE>
__global__ __launch_bounds__(256, 2)
void k_gemm(const float* __restrict__ Xin, const float* __restrict__ bias,
            float* __restrict__ Yout) {
    constexpr int WP = CK + 8;     // W smem pitch (bf16 elems)
    constexpr int XP = 72;         // X smem pitch
    constexpr int NCH = CK / 64;   // K chunks

    extern __shared__ char smem_raw[];
    __nv_bfloat16* sWh = (__nv_bfloat16*)smem_raw;
    __nv_bfloat16* sWl = sWh + 64 * WP;
    __nv_bfloat16* sXh = sWl + 64 * WP;
    __nv_bfloat16* sXl = sXh + 64 * XP;
    float* ssc = (float*)(sXl + 64 * XP);

    const int tid = threadIdx.x;
    const int lane = tid & 31;
    const int wid = tid >> 5;
    const int b = blockIdx.y;
    const int p0 = blockIdx.x * 64;

    const float* Xp = SCALE ? (const float*)g_edge : Xin;
    const __nv_bfloat16* gWh = SCALE ? g_wout_hi : g_win_hi;
    const __nv_bfloat16* gWl = SCALE ? g_wout_lo : g_win_lo;

    // Stage weights (bf16 hi/lo) into padded smem
    for (int i = tid; i < 64 * CK / 8; i += 256) {
        int m = i / (CK / 8);
        int c = (i % (CK / 8)) * 8;
        *(uint4*)&sWh[m * WP + c] = ((const uint4*)gWh)[i];
        *(uint4*)&sWl[m * WP + c] = ((const uint4*)gWl)[i];
    }
    if (SCALE && tid < CK) ssc[tid] = g_seff[b * CK + tid];

    // X chunk staging assignment: thread -> (k row, 16 n-values)
    const int kr = tid >> 2;
    const int nn = (tid & 3) * 16;
    float vv[16];
    {
        const float* xp = Xp + ((size_t)b * CK + kr) * HW + p0 + nn;
        float4 q0 = *(const float4*)(xp);
        float4 q1 = *(const float4*)(xp + 4);
        float4 q2 = *(const float4*)(xp + 8);
        float4 q3 = *(const float4*)(xp + 12);
        vv[0]=q0.x; vv[1]=q0.y; vv[2]=q0.z; vv[3]=q0.w;
        vv[4]=q1.x; vv[5]=q1.y; vv[6]=q1.z; vv[7]=q1.w;
        vv[8]=q2.x; vv[9]=q2.y; vv[10]=q2.z; vv[11]=q2.w;
        vv[12]=q3.x; vv[13]=q3.y; vv[14]=q3.z; vv[15]=q3.w;
    }
    __syncthreads();   // weights + ssc ready

    const uint32_t uWh = (uint32_t)__cvta_generic_to_shared(sWh);
    const uint32_t uWl = (uint32_t)__cvta_generic_to_shared(sWl);
    const uint32_t uXh = (uint32_t)__cvta_generic_to_shared(sXh);
    const uint32_t uXl = (uint32_t)__cvta_generic_to_shared(sXl);

    const int m0 = (wid & 1) * 32;
    const int nc0 = (wid >> 1) * 16;
    float d[2][2][4];
#pragma unroll
    for (int mt = 0; mt < 2; mt++)
#pragma unroll
        for (int nt = 0; nt < 2; nt++)
#pragma unroll
            for (int r = 0; r < 4; r++) d[mt][nt][r] = 0.0f;

    for (int ch = 0; ch < NCH; ch++) {
        // convert staged chunk to bf16 hi/lo and store
        {
            float s = 1.0f;
            if (SCALE) s = ssc[ch * 64 + kr];
            __nv_bfloat162 hb[8], lb[8];
#pragma unroll
            for (int j = 0; j < 8; j++) {
                float a = vv[2 * j] * (SCALE ? s : 1.0f);
                float c = vv[2 * j + 1] * (SCALE ? s : 1.0f);
                __nv_bfloat16 ah = __float2bfloat16_rn(a);
                __nv_bfloat16 ch_ = __float2bfloat16_rn(c);
                hb[j] = __nv_bfloat162(ah, ch_);
                lb[j] = __nv_bfloat162(__float2bfloat16_rn(a - __bfloat162float(ah)),
                                       __float2bfloat16_rn(c - __bfloat162float(ch_)));
            }
            int off = kr * XP + nn;
            *(uint4*)&sXh[off] = ((uint4*)hb)[0];
            *(uint4*)&sXh[off + 8] = ((uint4*)hb)[1];
            *(uint4*)&sXl[off] = ((uint4*)lb)[0];
            *(uint4*)&sXl[off + 8] = ((uint4*)lb)[1];
        }
        __syncthreads();

        // prefetch next chunk while MMAs run
        if (ch + 1 < NCH) {
            const float* xp = Xp + ((size_t)b * CK + (ch + 1) * 64 + kr) * HW + p0 + nn;
            float4 q0 = *(const float4*)(xp);
            float4 q1 = *(const float4*)(xp + 4);
            float4 q2 = *(const float4*)(xp + 8);
            float4 q3 = *(const float4*)(xp + 12);
            vv[0]=q0.x; vv[1]=q0.y; vv[2]=q0.z; vv[3]=q0.w;
            vv[4]=q1.x; vv[5]=q1.y; vv[6]=q1.z; vv[7]=q1.w;
            vv[8]=q2.x; vv[9]=q2.y; vv[10]=q2.z; vv[11]=q2.w;
            vv[12]=q3.x; vv[13]=q3.y; vv[14]=q3.z; vv[15]=q3.w;
        }

#pragma unroll
        for (int ks = 0; ks < 4; ks++) {
            const int kk = ch * 64 + ks * 16;
            uint32_t ah[2][4], al[2][4];
#pragma unroll
            for (int mt = 0; mt < 2; mt++) {
                int arow = m0 + mt * 16 + (lane & 15);
                int acol = kk + (lane >> 4) * 8;
                uint32_t aoff = (uint32_t)(arow * WP + acol) * 2;
                ldsm_x4(ah[mt], uWh + aoff);
                ldsm_x4(al[mt], uWl + aoff);
            }
            uint32_t bh[2][2], bl[2][2];
#pragma unroll
            for (int nt = 0; nt < 2; nt++) {
                int brow = ks * 16 + (lane & 15);
                int bcol = nc0 + nt * 8;
                uint32_t boff = (uint32_t)(brow * XP + bcol) * 2;
                ldsm_x2t(bh[nt], uXh + boff);
                ldsm_x2t(bl[nt], uXl + boff);
            }
#pragma unroll
            for (int mt = 0; mt < 2; mt++)
#pragma unroll
                for (int nt = 0; nt < 2; nt++) {
                    mma_bf16(d[mt][nt], ah[mt], bh[nt]);
                    mma_bf16(d[mt][nt], ah[mt], bl[nt]);
                    mma_bf16(d[mt][nt], al[mt], bh[nt]);
                }
        }
        __syncthreads();
    }

    // Epilogue: add bias, store fp32
    float* Yp = SCALE ? Yout : g_y;
    const int rr = lane >> 2;
    const int cq = (lane & 3) * 2;
#pragma unroll
    for (int mt = 0; mt < 2; mt++) {
        int m = m0 + mt * 16 + rr;
        float bv0 = __ldg(bias + m);
        float bv1 = __ldg(bias + m + 8);
#pragma unroll
        for (int nt = 0; nt < 2; nt++) {
            int n = nc0 + nt * 8 + cq;
            float2 v0 = make_float2(d[mt][nt][0] + bv0, d[mt][nt][1] + bv0);
            float2 v1 = make_float2(d[mt][nt][2] + bv1, d[mt][nt][3] + bv1);
            *(float2*)&Yp[((size_t)b * 64 + m) * HW + p0 + n] = v0;
            *(float2*)&Yp[((size_t)b * 64 + m + 8) * HW + p0 + n] = v1;
        }
    }
}

// ---------------------------------------------------------------------------
// Stage B: per (b,c) plane, 32x32 tiles with radius-3 halo:
//   sm = gauss5x5(y) (separable), edge = max(|scharr0|,|scharr90|) + 0.1|lap|
// ---------------------------------------------------------------------------
__global__ __launch_bounds__(256)
void k_edge() {
    __shared__ float sy[38 * 40];
    __shared__ float sh[38 * 34];
    __shared__ float s2[34 * 36];
    __shared__ float red[256];

    const int tid = threadIdx.x;
    const int z = blockIdx.z;
    const int ty = blockIdx.y, tx = blockIdx.x;
    const float* yp = g_y + (size_t)z * HW;
    const int gy0 = ty * 32 - 3, gx0 = tx * 32 - 3;

    for (int idx = tid; idx < 38 * 38; idx += 256) {
        int r = idx / 38, c = idx % 38;
        int gy = gy0 + r, gx = gx0 + c;
        float v = 0.0f;
        if (gy >= 0 && gy < IMG && gx >= 0 && gx < IMG) v = yp[gy * IMG + gx];
        sy[r * 40 + c] = v;
    }
    __syncthreads();

    for (int idx = tid; idx < 38 * 34; idx += 256) {
        int r = idx / 34, c = idx % 34;
        const float* row = sy + r * 40 + c;
        sh[idx] = G0 * (row[0] + row[4]) + G1 * (row[1] + row[3]) + G2 * row[2];
    }
    __syncthreads();

    for (int idx = tid; idx < 34 * 34; idx += 256) {
        int r = idx / 34, c = idx % 34;
        int gy = ty * 32 + r - 1, gx = tx * 32 + c - 1;
        float v = 0.0f;
        if (gy >= 0 && gy < IMG && gx >= 0 && gx < IMG) {
            const float* col = sh + r * 34 + c;
            v = G0 * (col[0] + col[4 * 34]) + G1 * (col[34] + col[3 * 34])
                + G2 * col[2 * 34];
        }
        s2[r * 36 + c] = v;
    }
    __syncthreads();

    float tmax = 0.0f, tsum = 0.0f;
    float* ep = g_edge + (size_t)z * HW;
#pragma unroll
    for (int q = 0; q < 4; q++) {
        int idx = q * 256 + tid;
        int i = idx >> 5, j = idx & 31;
        const float* s = s2 + i * 36 + j;
        float nw = s[0],  nn = s[1],  ne = s[2];
        float ww = s[36], cc = s[37], ee = s[38];
        float sw_ = s[72], ss = s[73], se = s[74];
        float gx = 3.0f * (nw - ne) + 10.0f * (ww - ee) + 3.0f * (sw_ - se);
        float gy = 3.0f * (nw - sw_) + 10.0f * (nn - ss) + 3.0f * (ne - se);
        float lap = 4.0f * cc - nn - ss - ww - ee;
        float e = fmaxf(fabsf(gx), fabsf(gy)) + 0.1f * fabsf(lap);
        ep[(ty * 32 + i) * IMG + tx * 32 + j] = e;
        tmax = fmaxf(tmax, e);
        tsum += e;
    }

    red[tid] = tmax;
    __syncthreads();
    for (int s = 128; s; s >>= 1) {
        if (tid < s) red[tid] = fmaxf(red[tid], red[tid + s]);
        __syncthreads();
    }
    if (tid == 0) atomicMax(&g_maxbits, __float_as_uint(red[0]));
    __syncthreads();
    red[tid] = tsum;
    __syncthreads();
    for (int s = 128; s; s >>= 1) {
        if (tid < s) red[tid] += red[tid + s];
        __syncthreads();
    }
    if (tid == 0) atomicAdd(&g_csum[z], red[0]);
}

// ---------------------------------------------------------------------------
// Stage C: SE head.
// ---------------------------------------------------------------------------
__global__ void k_se(const float* __restrict__ w_fc1, const float* __restrict__ b_fc1,
                     const float* __restrict__ w_fc2, const float* __restrict__ b_fc2) {
    __shared__ float pooled[NB * CMID];
    __shared__ float hbuf[NB * 4];
    const int tid = threadIdx.x;
    const float maxv = __uint_as_float(g_maxbits);
    const float inv = 1.0f / (maxv + 1e-8f);

    pooled[tid] = g_csum[tid] * inv * (1.0f / 65536.0f);
    __syncthreads();
    if (tid < NB * 4) {
        int b = tid >> 2, j = tid & 3;
        float a = b_fc1[j];
        for (int c = 0; c < 64; c++) a += w_fc1[j * 64 + c] * pooled[b * 64 + c];
        hbuf[tid] = a > 0.0f ? a : 0.0f;
    }
    __syncthreads();
    {
        int b = tid >> 6, c = tid & 63;
        float a = b_fc2[c];
        for (int j = 0; j < 4; j++) a += w_fc2[c * 4 + j] * hbuf[b * 4 + j];
        float sc = 1.0f / (1.0f + expf(-a));
        g_seff[tid] = sc * inv;
    }
}

// ---------------------------------------------------------------------------
extern "C" void kernel_launch(void* const* d_in, const int* in_sizes, int n_in,
                              void* d_out, int out_size) {
    const float* x     = (const float*)d_in[0];
    const float* w_in  = (const float*)d_in[1];
    const float* b_in  = (const float*)d_in[2];
    const float* w_fc1 = (const float*)d_in[3];
    const float* b_fc1 = (const float*)d_in[4];
    const float* w_fc2 = (const float*)d_in[5];
    const float* b_fc2 = (const float*)d_in[6];
    const float* w_out = (const float*)d_in[7];
    const float* b_out = (const float*)d_in[8];
    float* out = (float*)d_out;

    const int SM_IN  = (2 * 64 * (256 + 8) + 2 * 64 * 72) * 2;          // 86016
    const int SM_OUT = (2 * 64 * (64 + 8) + 2 * 64 * 72) * 2 + 64 * 4;  // 37120
    cudaFuncSetAttribute((const void*)k_gemm<256, false>,
                         cudaFuncAttributeMaxDynamicSharedMemorySize, SM_IN);
    cudaFuncSetAttribute((const void*)k_gemm<64, true>,
                         cudaFuncAttributeMaxDynamicSharedMemorySize, SM_OUT);

    k_init<<<1, 256>>>();
    k_prep<<<64, 256>>>(w_in, w_out);
    dim3 ga(1024, NB);
    k_gemm<256, false><<<ga, 256, SM_IN>>>(x, b_in, nullptr);
    dim3 gb(8, 8, NB * CMID);
    k_edge<<<gb, 256>>>();
    k_se<<<1, 256>>>(w_fc1, b_fc1, w_fc2, b_fc2);
    k_gemm<64, true><<<ga, 256, SM_OUT>>>(nullptr, b_out, out);
}